// round 1
// baseline (speedup 1.0000x reference)
#include <cuda_runtime.h>

// TextEmbedding: gather [B,S,W,D] from table, per-token LayerNorm, sum over W.
// B=32, S=128, W=32, D=256  -> out [B*S, D] f32.
//
// Layout: 1 block per (b,s) position. 8 warps; warp w handles words w, w+8,
// w+16, w+24. Each lane owns 8 contiguous dims (2x float4) -> warp reads a
// full 1KB table row coalesced. Warp shfl reduction for mean/var; register
// accumulation of the word-sum; single smem stage to combine the 8 warps.

#define DIM 256
#define WORDS 32
#define EPS 1e-12f

__global__ __launch_bounds__(256, 8)
void emb_ln_sum_kernel(const int* __restrict__ ids,
                       const float* __restrict__ table,
                       const float* __restrict__ gamma,
                       const float* __restrict__ beta,
                       float* __restrict__ out) {
    __shared__ float smem[8 * DIM];

    const int pos  = blockIdx.x;          // 0..4095
    const int tid  = threadIdx.x;
    const int warp = tid >> 5;
    const int lane = tid & 31;
    const int dbase = lane * 8;

    // gamma/beta for this lane's 8 dims (vectorized)
    float4 g0 = *(const float4*)(gamma + dbase);
    float4 g1 = *(const float4*)(gamma + dbase + 4);
    float4 b0 = *(const float4*)(beta  + dbase);
    float4 b1 = *(const float4*)(beta  + dbase + 4);
    const float g[8]  = {g0.x, g0.y, g0.z, g0.w, g1.x, g1.y, g1.z, g1.w};
    const float bt[8] = {b0.x, b0.y, b0.z, b0.w, b1.x, b1.y, b1.z, b1.w};

    float acc[8];
    #pragma unroll
    for (int i = 0; i < 8; i++) acc[i] = 0.0f;

    const int* my_ids = ids + pos * WORDS;

    #pragma unroll
    for (int wi = 0; wi < WORDS / 8; wi++) {
        const int w  = warp + wi * 8;
        const int id = __ldg(my_ids + w);
        const float4* row = (const float4*)(table + (long long)id * DIM + dbase);
        float4 a = __ldg(row);
        float4 b = __ldg(row + 1);
        float x[8] = {a.x, a.y, a.z, a.w, b.x, b.y, b.z, b.w};

        float s = 0.0f, sq = 0.0f;
        #pragma unroll
        for (int i = 0; i < 8; i++) { s += x[i]; sq = fmaf(x[i], x[i], sq); }
        #pragma unroll
        for (int off = 16; off; off >>= 1) {
            s  += __shfl_xor_sync(0xffffffffu, s,  off);
            sq += __shfl_xor_sync(0xffffffffu, sq, off);
        }
        const float mu   = s  * (1.0f / 256.0f);
        const float var  = sq * (1.0f / 256.0f) - mu * mu;
        const float rstd = rsqrtf(var + EPS);

        #pragma unroll
        for (int i = 0; i < 8; i++)
            acc[i] += (x[i] - mu) * rstd * g[i] + bt[i];
    }

    // Combine the 8 warps via shared memory
    float* sp = smem + warp * DIM + dbase;
    *(float4*)(sp)     = make_float4(acc[0], acc[1], acc[2], acc[3]);
    *(float4*)(sp + 4) = make_float4(acc[4], acc[5], acc[6], acc[7]);
    __syncthreads();

    float r = 0.0f;
    #pragma unroll
    for (int w = 0; w < 8; w++) r += smem[w * DIM + tid];
    out[pos * DIM + tid] = r;
}

extern "C" void kernel_launch(void* const* d_in, const int* in_sizes, int n_in,
                              void* d_out, int out_size) {
    const int*   ids   = (const int*)d_in[0];     // [32,128,32] int32
    const float* table = (const float*)d_in[1];   // [32000,256] f32
    const float* gamma = (const float*)d_in[2];   // [256]
    const float* beta  = (const float*)d_in[3];   // [256]
    float* out = (float*)d_out;                   // [32,128,256] f32

    const int n_pos = in_sizes[0] / WORDS;        // 4096
    emb_ln_sum_kernel<<<n_pos, 256>>>(ids, table, gamma, beta, out);
}

// round 2
// speedup vs baseline: 1.9238x; 1.9238x over previous
#include <cuda_runtime.h>

// TextEmbedding: gather [B,S,W,D] from table, per-token LayerNorm, sum over W.
// B=32, S=128, W=32, D=256  -> out [B*S, D] f32.
//
// R2: batch all row loads per warp up front (MLP=8 LDG.128), interleave the
// 4 words' shuffle-reduction chains, factor gamma/beta out of the word loop
// (out = sum(xn)*gamma + 32*beta).

#define DIM 256
#define WORDS 32
#define EPS 1e-12f

__global__ __launch_bounds__(256, 4)
void emb_ln_sum_kernel(const int* __restrict__ ids,
                       const float* __restrict__ table,
                       const float* __restrict__ gamma,
                       const float* __restrict__ beta,
                       float* __restrict__ out) {
    __shared__ float smem[8 * DIM];

    const int pos   = blockIdx.x;          // 0..4095
    const int tid   = threadIdx.x;
    const int warp  = tid >> 5;
    const int lane  = tid & 31;
    const int dbase = lane * 8;

    const int* my_ids = ids + pos * WORDS;

    // Load all 4 word ids for this warp (broadcast loads)
    int id[4];
    #pragma unroll
    for (int wi = 0; wi < 4; wi++) id[wi] = __ldg(my_ids + warp + wi * 8);

    // Issue ALL 8 row loads before any consumption (MLP=8)
    float4 va[4], vb[4];
    #pragma unroll
    for (int wi = 0; wi < 4; wi++) {
        const float4* row = (const float4*)(table + (size_t)id[wi] * DIM + dbase);
        va[wi] = __ldg(row);
        vb[wi] = __ldg(row + 1);
    }

    // Per-word lane-partial sums
    float s[4], sq[4];
    #pragma unroll
    for (int wi = 0; wi < 4; wi++) {
        float4 a = va[wi], b = vb[wi];
        float ss = a.x + a.y + a.z + a.w + b.x + b.y + b.z + b.w;
        float qq = a.x*a.x;
        qq = fmaf(a.y, a.y, qq); qq = fmaf(a.z, a.z, qq); qq = fmaf(a.w, a.w, qq);
        qq = fmaf(b.x, b.x, qq); qq = fmaf(b.y, b.y, qq);
        qq = fmaf(b.z, b.z, qq); qq = fmaf(b.w, b.w, qq);
        s[wi] = ss; sq[wi] = qq;
    }

    // Interleaved butterfly reduction: 4 independent chains per level
    #pragma unroll
    for (int off = 16; off; off >>= 1) {
        #pragma unroll
        for (int wi = 0; wi < 4; wi++) {
            s[wi]  += __shfl_xor_sync(0xffffffffu, s[wi],  off);
            sq[wi] += __shfl_xor_sync(0xffffffffu, sq[wi], off);
        }
    }

    // Normalize and accumulate (gamma/beta factored out)
    float acc[8];
    #pragma unroll
    for (int i = 0; i < 8; i++) acc[i] = 0.0f;

    #pragma unroll
    for (int wi = 0; wi < 4; wi++) {
        const float mu   = s[wi]  * (1.0f / 256.0f);
        const float var  = sq[wi] * (1.0f / 256.0f) - mu * mu;
        const float rstd = rsqrtf(var + EPS);
        const float mshift = -mu * rstd;
        float4 a = va[wi], b = vb[wi];
        acc[0] += fmaf(a.x, rstd, mshift);
        acc[1] += fmaf(a.y, rstd, mshift);
        acc[2] += fmaf(a.z, rstd, mshift);
        acc[3] += fmaf(a.w, rstd, mshift);
        acc[4] += fmaf(b.x, rstd, mshift);
        acc[5] += fmaf(b.y, rstd, mshift);
        acc[6] += fmaf(b.z, rstd, mshift);
        acc[7] += fmaf(b.w, rstd, mshift);
    }

    // Combine the 8 warps via shared memory
    float* sp = smem + warp * DIM + dbase;
    *(float4*)(sp)     = make_float4(acc[0], acc[1], acc[2], acc[3]);
    *(float4*)(sp + 4) = make_float4(acc[4], acc[5], acc[6], acc[7]);
    __syncthreads();

    float r = 0.0f;
    #pragma unroll
    for (int w = 0; w < 8; w++) r += smem[w * DIM + tid];

    out[pos * DIM + tid] = fmaf(r, __ldg(gamma + tid), 32.0f * __ldg(beta + tid));
}

extern "C" void kernel_launch(void* const* d_in, const int* in_sizes, int n_in,
                              void* d_out, int out_size) {
    const int*   ids   = (const int*)d_in[0];     // [32,128,32] int32
    const float* table = (const float*)d_in[1];   // [32000,256] f32
    const float* gamma = (const float*)d_in[2];   // [256]
    const float* beta  = (const float*)d_in[3];   // [256]
    float* out = (float*)d_out;                   // [32,128,256] f32

    const int n_pos = in_sizes[0] / WORDS;        // 4096
    emb_ln_sum_kernel<<<n_pos, 256>>>(ids, table, gamma, beta, out);
}

// round 4
// speedup vs baseline: 2.3589x; 1.2262x over previous
#include <cuda_runtime.h>

// TextEmbedding: gather [B,S,W,D] from table, per-token LayerNorm, sum over W.
// B=32, S=128, W=32, D=256  -> out [B*S, D] f32.
//
// R4: fully-coalesced row loads (lane owns dims 4L..4L+3 and 128+4L..),
// fold-style warp reduction (16 shfl + 1 rsqrt per warp instead of
// 40 shfl + 4 rsqrt), MLP=8 batched loads, gamma/beta factored out.

#define DIM 256
#define WORDS 32
#define EPS 1e-12f

__global__ __launch_bounds__(256, 4)
void emb_ln_sum_kernel(const int* __restrict__ ids,
                       const float* __restrict__ table,
                       const float* __restrict__ gamma,
                       const float* __restrict__ beta,
                       float* __restrict__ out) {
    __shared__ float smem[8 * DIM];

    const int pos  = blockIdx.x;          // 0..4095
    const int tid  = threadIdx.x;
    const int warp = tid >> 5;
    const int lane = tid & 31;

    // Warp w handles words 4w..4w+3: one int4 broadcast load.
    const int4 idv = __ldg((const int4*)(ids + pos * WORDS) + warp);
    const int id[4] = {idv.x, idv.y, idv.z, idv.w};

    // All 8 row loads upfront (MLP=8), each LDG.128 fully coalesced (512B).
    float4 va[4], vb[4];
    #pragma unroll
    for (int wi = 0; wi < 4; wi++) {
        const float4* row = (const float4*)(table + (size_t)id[wi] * DIM);
        va[wi] = __ldg(row + lane);        // dims [4*lane, 4*lane+4)
        vb[wi] = __ldg(row + 32 + lane);   // dims [128+4*lane, ...)
    }

    // Per-lane partials, ordered v = {s0,q0, s1,q1, s2,q2, s3,q3}
    float v[8];
    #pragma unroll
    for (int wi = 0; wi < 4; wi++) {
        float4 a = va[wi], b = vb[wi];
        float ss = ((a.x + a.y) + (a.z + a.w)) + ((b.x + b.y) + (b.z + b.w));
        float qq = a.x * a.x;
        qq = fmaf(a.y, a.y, qq); qq = fmaf(a.z, a.z, qq); qq = fmaf(a.w, a.w, qq);
        qq = fmaf(b.x, b.x, qq); qq = fmaf(b.y, b.y, qq);
        qq = fmaf(b.z, b.z, qq); qq = fmaf(b.w, b.w, qq);
        v[2 * wi] = ss; v[2 * wi + 1] = qq;
    }

    // Fold reduction: 8 values -> 1 per lane across lane bits 16, 8, 4.
    const bool hi16 = (lane & 16) != 0;
    float w4[4];
    #pragma unroll
    for (int j = 0; j < 4; j++) {
        float send = hi16 ? v[j] : v[j + 4];
        float keep = hi16 ? v[j + 4] : v[j];
        w4[j] = keep + __shfl_xor_sync(0xffffffffu, send, 16);
    }
    const bool hi8 = (lane & 8) != 0;
    float w2[2];
    #pragma unroll
    for (int j = 0; j < 2; j++) {
        float send = hi8 ? w4[j] : w4[j + 2];
        float keep = hi8 ? w4[j + 2] : w4[j];
        w2[j] = keep + __shfl_xor_sync(0xffffffffu, send, 8);
    }
    const bool hi4 = (lane & 4) != 0;
    float y;
    {
        float send = hi4 ? w2[0] : w2[1];
        float keep = hi4 ? w2[1] : w2[0];
        y = keep + __shfl_xor_sync(0xffffffffu, send, 4);
    }
    // Butterfly remaining lane bits 2, 1 -> full sum in every lane of group.
    y += __shfl_xor_sync(0xffffffffu, y, 2);
    y += __shfl_xor_sync(0xffffffffu, y, 1);
    // Lane now holds: word W = 2*b16 + b8; b4 = 0 -> s_W, b4 = 1 -> q_W.

    // Pair s/q, compute rstd + shift once per lane.
    const float p  = __shfl_xor_sync(0xffffffffu, y, 4);
    const float s_ = hi4 ? p : y;
    const float q_ = hi4 ? y : p;
    const float mu  = s_ * (1.0f / 256.0f);
    const float var = q_ * (1.0f / 256.0f) - mu * mu;
    const float r_  = rsqrtf(var + EPS);
    const float msh = -mu * r_;

    // Total shift over this warp's 4 words (sum distinct word groups: bits 8,16)
    float mtot = msh + __shfl_xor_sync(0xffffffffu, msh, 8);
    mtot += __shfl_xor_sync(0xffffffffu, mtot, 16);

    // Broadcast rstd for words 0..3 (source lanes 0, 8, 16, 24).
    float rstd[4];
    #pragma unroll
    for (int w_ = 0; w_ < 4; w_++)
        rstd[w_] = __shfl_sync(0xffffffffu, r_, w_ * 8);

    // acc[i] = mtot + sum_w x_w[i] * rstd_w
    float acc[8];
    #pragma unroll
    for (int i = 0; i < 8; i++) acc[i] = mtot;
    #pragma unroll
    for (int wi = 0; wi < 4; wi++) {
        float4 a = va[wi], b = vb[wi];
        const float r = rstd[wi];
        acc[0] = fmaf(a.x, r, acc[0]);
        acc[1] = fmaf(a.y, r, acc[1]);
        acc[2] = fmaf(a.z, r, acc[2]);
        acc[3] = fmaf(a.w, r, acc[3]);
        acc[4] = fmaf(b.x, r, acc[4]);
        acc[5] = fmaf(b.y, r, acc[5]);
        acc[6] = fmaf(b.z, r, acc[6]);
        acc[7] = fmaf(b.w, r, acc[7]);
    }

    // Combine the 8 warps via shared memory (coalesced STS.128).
    float* sp = smem + warp * DIM;
    *(float4*)(sp + 4 * lane)       = make_float4(acc[0], acc[1], acc[2], acc[3]);
    *(float4*)(sp + 128 + 4 * lane) = make_float4(acc[4], acc[5], acc[6], acc[7]);
    __syncthreads();

    float r = 0.0f;
    #pragma unroll
    for (int w = 0; w < 8; w++) r += smem[w * DIM + tid];

    out[pos * DIM + tid] = fmaf(r, __ldg(gamma + tid), 32.0f * __ldg(beta + tid));
}

extern "C" void kernel_launch(void* const* d_in, const int* in_sizes, int n_in,
                              void* d_out, int out_size) {
    const int*   ids   = (const int*)d_in[0];     // [32,128,32] int32
    const float* table = (const float*)d_in[1];   // [32000,256] f32
    const float* gamma = (const float*)d_in[2];   // [256]
    const float* beta  = (const float*)d_in[3];   // [256]
    float* out = (float*)d_out;                   // [32,128,256] f32

    const int n_pos = in_sizes[0] / WORDS;        // 4096
    emb_ln_sum_kernel<<<n_pos, 256>>>(ids, table, gamma, beta, out);
}

// round 5
// speedup vs baseline: 2.3856x; 1.0113x over previous
#include <cuda_runtime.h>

// TextEmbedding: gather [B,S,W,D] from table, per-token LayerNorm, sum over W.
// B=32, S=128, W=32, D=256  -> out [B*S, D] f32.
//
// R5: packed f32x2 math (FFMA2/FADD2, sm_103a) for partial sums and the
// word-sum accumulate; coalesced LDG.128 gather; fold warp reduction;
// occupancy 5 CTAs/SM.

#define DIM 256
#define WORDS 32
#define EPS 1e-12f

typedef unsigned long long u64;

__device__ __forceinline__ u64 pack2(float lo, float hi) {
    u64 r; asm("mov.b64 %0, {%1, %2};" : "=l"(r) : "f"(lo), "f"(hi)); return r;
}
__device__ __forceinline__ void unpack2(u64 v, float& lo, float& hi) {
    asm("mov.b64 {%0, %1}, %2;" : "=f"(lo), "=f"(hi) : "l"(v));
}
__device__ __forceinline__ u64 add2(u64 a, u64 b) {
    u64 d; asm("add.rn.f32x2 %0, %1, %2;" : "=l"(d) : "l"(a), "l"(b)); return d;
}
__device__ __forceinline__ u64 mul2(u64 a, u64 b) {
    u64 d; asm("mul.rn.f32x2 %0, %1, %2;" : "=l"(d) : "l"(a), "l"(b)); return d;
}
__device__ __forceinline__ u64 fma2(u64 a, u64 b, u64 c) {
    u64 d; asm("fma.rn.f32x2 %0, %1, %2, %3;" : "=l"(d) : "l"(a), "l"(b), "l"(c)); return d;
}

__global__ __launch_bounds__(256, 5)
void emb_ln_sum_kernel(const int* __restrict__ ids,
                       const float* __restrict__ table,
                       const float* __restrict__ gamma,
                       const float* __restrict__ beta,
                       float* __restrict__ out) {
    __shared__ float smem[8 * DIM];

    const int pos  = blockIdx.x;          // 0..4095
    const int tid  = threadIdx.x;
    const int warp = tid >> 5;
    const int lane = tid & 31;

    // Warp w handles words 4w..4w+3: one int4 broadcast load.
    const int4 idv = __ldg((const int4*)(ids + pos * WORDS) + warp);
    const int id[4] = {idv.x, idv.y, idv.z, idv.w};

    // All 8 row loads upfront (MLP=8), each LDG.128 fully coalesced (512B).
    float4 va[4], vb[4];
    #pragma unroll
    for (int wi = 0; wi < 4; wi++) {
        const float4* row = (const float4*)(table + (size_t)id[wi] * DIM);
        va[wi] = __ldg(row + lane);        // dims [4*lane, 4*lane+4)
        vb[wi] = __ldg(row + 32 + lane);   // dims [128+4*lane, ...)
    }

    // Per-lane partials via packed f32x2: v = {s0,q0, s1,q1, s2,q2, s3,q3}
    float v[8];
    #pragma unroll
    for (int wi = 0; wi < 4; wi++) {
        const u64 a01 = pack2(va[wi].x, va[wi].y);
        const u64 a23 = pack2(va[wi].z, va[wi].w);
        const u64 b01 = pack2(vb[wi].x, vb[wi].y);
        const u64 b23 = pack2(vb[wi].z, vb[wi].w);
        const u64 s2 = add2(add2(a01, a23), add2(b01, b23));
        const u64 q2 = fma2(a01, a01, fma2(a23, a23, fma2(b01, b01, mul2(b23, b23))));
        float sl, sh, ql, qh;
        unpack2(s2, sl, sh); unpack2(q2, ql, qh);
        v[2 * wi] = sl + sh; v[2 * wi + 1] = ql + qh;
    }

    // Fold reduction: 8 values -> 1 per lane across lane bits 16, 8, 4.
    const bool hi16 = (lane & 16) != 0;
    float w4[4];
    #pragma unroll
    for (int j = 0; j < 4; j++) {
        float send = hi16 ? v[j] : v[j + 4];
        float keep = hi16 ? v[j + 4] : v[j];
        w4[j] = keep + __shfl_xor_sync(0xffffffffu, send, 16);
    }
    const bool hi8 = (lane & 8) != 0;
    float w2[2];
    #pragma unroll
    for (int j = 0; j < 2; j++) {
        float send = hi8 ? w4[j] : w4[j + 2];
        float keep = hi8 ? w4[j + 2] : w4[j];
        w2[j] = keep + __shfl_xor_sync(0xffffffffu, send, 8);
    }
    const bool hi4 = (lane & 4) != 0;
    float y;
    {
        float send = hi4 ? w2[0] : w2[1];
        float keep = hi4 ? w2[1] : w2[0];
        y = keep + __shfl_xor_sync(0xffffffffu, send, 4);
    }
    y += __shfl_xor_sync(0xffffffffu, y, 2);
    y += __shfl_xor_sync(0xffffffffu, y, 1);
    // Lane holds: word W = 2*b16 + b8; b4=0 -> s_W, b4=1 -> q_W.

    const float p  = __shfl_xor_sync(0xffffffffu, y, 4);
    const float s_ = hi4 ? p : y;
    const float q_ = hi4 ? y : p;
    const float mu  = s_ * (1.0f / 256.0f);
    const float var = q_ * (1.0f / 256.0f) - mu * mu;
    const float r_  = rsqrtf(var + EPS);
    const float msh = -mu * r_;

    // Total shift over this warp's 4 words.
    float mtot = msh + __shfl_xor_sync(0xffffffffu, msh, 8);
    mtot += __shfl_xor_sync(0xffffffffu, mtot, 16);

    // Broadcast rstd for words 0..3 (source lanes 0, 8, 16, 24).
    float rstd[4];
    #pragma unroll
    for (int w_ = 0; w_ < 4; w_++)
        rstd[w_] = __shfl_sync(0xffffffffu, r_, w_ * 8);

    // acc = (mtot,mtot) + sum_w x_w * (rstd_w, rstd_w)   [packed FFMA2]
    const u64 minit = pack2(mtot, mtot);
    u64 acc[4] = {minit, minit, minit, minit};
    #pragma unroll
    for (int wi = 0; wi < 4; wi++) {
        const u64 rr = pack2(rstd[wi], rstd[wi]);
        acc[0] = fma2(pack2(va[wi].x, va[wi].y), rr, acc[0]);
        acc[1] = fma2(pack2(va[wi].z, va[wi].w), rr, acc[1]);
        acc[2] = fma2(pack2(vb[wi].x, vb[wi].y), rr, acc[2]);
        acc[3] = fma2(pack2(vb[wi].z, vb[wi].w), rr, acc[3]);
    }

    // Combine the 8 warps via shared memory (coalesced 16B stores).
    float* sp = smem + warp * DIM;
    *(ulonglong2*)(sp + 4 * lane)       = make_ulonglong2(acc[0], acc[1]);
    *(ulonglong2*)(sp + 128 + 4 * lane) = make_ulonglong2(acc[2], acc[3]);
    __syncthreads();

    float r = 0.0f;
    #pragma unroll
    for (int w = 0; w < 8; w++) r += smem[w * DIM + tid];

    out[pos * DIM + tid] = fmaf(r, __ldg(gamma + tid), 32.0f * __ldg(beta + tid));
}

extern "C" void kernel_launch(void* const* d_in, const int* in_sizes, int n_in,
                              void* d_out, int out_size) {
    const int*   ids   = (const int*)d_in[0];     // [32,128,32] int32
    const float* table = (const float*)d_in[1];   // [32000,256] f32
    const float* gamma = (const float*)d_in[2];   // [256]
    const float* beta  = (const float*)d_in[3];   // [256]
    float* out = (float*)d_out;                   // [32,128,256] f32

    const int n_pos = in_sizes[0] / WORDS;        // 4096
    emb_ln_sum_kernel<<<n_pos, 256>>>(ids, table, gamma, beta, out);
}

// round 6
// speedup vs baseline: 2.7198x; 1.1401x over previous
#include <cuda_runtime.h>

// TextEmbedding: gather [B,S,W,D] from table, per-token LayerNorm, sum over W.
// B=32, S=128, W=32, D=256  -> out [B*S, D] f32.
//
// R6: warp-per-position with 2-deep software-pipelined chunk loads.
// Each warp owns one (b,s) position: 8 chunks x 4 words. Chunk c+1's 8
// coalesced LDG.128 are issued before chunk c's fold reduction, hiding L2
// latency under the shuffle chain. No __syncthreads, no smem combine.
// ids: one LDG.32 per lane (lane L holds id[L]), extracted via shfl.

#define DIM 256
#define WORDS 32
#define EPS 1e-12f

typedef unsigned long long u64;

__device__ __forceinline__ u64 pack2(float lo, float hi) {
    u64 r; asm("mov.b64 %0, {%1, %2};" : "=l"(r) : "f"(lo), "f"(hi)); return r;
}
__device__ __forceinline__ void unpack2(u64 v, float& lo, float& hi) {
    asm("mov.b64 {%0, %1}, %2;" : "=f"(lo), "=f"(hi) : "l"(v));
}
__device__ __forceinline__ u64 add2(u64 a, u64 b) {
    u64 d; asm("add.rn.f32x2 %0, %1, %2;" : "=l"(d) : "l"(a), "l"(b)); return d;
}
__device__ __forceinline__ u64 mul2(u64 a, u64 b) {
    u64 d; asm("mul.rn.f32x2 %0, %1, %2;" : "=l"(d) : "l"(a), "l"(b)); return d;
}
__device__ __forceinline__ u64 fma2(u64 a, u64 b, u64 c) {
    u64 d; asm("fma.rn.f32x2 %0, %1, %2, %3;" : "=l"(d) : "l"(a), "l"(b), "l"(c)); return d;
}

// Issue the 8 coalesced row loads for chunk c (words 4c..4c+3).
__device__ __forceinline__ void load_chunk(const float* __restrict__ table,
                                           int id_lane, int c, int lane,
                                           float4 R[8]) {
    #pragma unroll
    for (int j = 0; j < 4; j++) {
        const int id = __shfl_sync(0xffffffffu, id_lane, 4 * c + j);
        const float4* row = (const float4*)(table + (size_t)id * DIM);
        R[j]     = __ldg(row + lane);        // dims [4*lane, 4*lane+4)
        R[4 + j] = __ldg(row + 32 + lane);   // dims [128+4*lane, ...)
    }
}

// Reduce 4 words in R: update acc[0..3] (u64 f32x2 pairs) and mtot.
__device__ __forceinline__ void process_chunk(const float4 R[8], int lane,
                                              u64 acc[4], float& mtot) {
    // Per-lane partials: v = {s0,q0, s1,q1, s2,q2, s3,q3}
    float v[8];
    #pragma unroll
    for (int wi = 0; wi < 4; wi++) {
        const u64 a01 = pack2(R[wi].x, R[wi].y);
        const u64 a23 = pack2(R[wi].z, R[wi].w);
        const u64 b01 = pack2(R[4 + wi].x, R[4 + wi].y);
        const u64 b23 = pack2(R[4 + wi].z, R[4 + wi].w);
        const u64 s2 = add2(add2(a01, a23), add2(b01, b23));
        const u64 q2 = fma2(a01, a01, fma2(a23, a23, fma2(b01, b01, mul2(b23, b23))));
        float sl, sh, ql, qh;
        unpack2(s2, sl, sh); unpack2(q2, ql, qh);
        v[2 * wi] = sl + sh; v[2 * wi + 1] = ql + qh;
    }

    // Fold reduction across lane bits 16, 8, 4; butterfly 2, 1.
    const bool hi16 = (lane & 16) != 0;
    float w4[4];
    #pragma unroll
    for (int j = 0; j < 4; j++) {
        float send = hi16 ? v[j] : v[j + 4];
        float keep = hi16 ? v[j + 4] : v[j];
        w4[j] = keep + __shfl_xor_sync(0xffffffffu, send, 16);
    }
    const bool hi8 = (lane & 8) != 0;
    float w2[2];
    #pragma unroll
    for (int j = 0; j < 2; j++) {
        float send = hi8 ? w4[j] : w4[j + 2];
        float keep = hi8 ? w4[j + 2] : w4[j];
        w2[j] = keep + __shfl_xor_sync(0xffffffffu, send, 8);
    }
    const bool hi4 = (lane & 4) != 0;
    float y;
    {
        float send = hi4 ? w2[0] : w2[1];
        float keep = hi4 ? w2[1] : w2[0];
        y = keep + __shfl_xor_sync(0xffffffffu, send, 4);
    }
    y += __shfl_xor_sync(0xffffffffu, y, 2);
    y += __shfl_xor_sync(0xffffffffu, y, 1);
    // Lane holds: word W = 2*b16 + b8; b4=0 -> s_W, b4=1 -> q_W.

    const float p  = __shfl_xor_sync(0xffffffffu, y, 4);
    const float s_ = hi4 ? p : y;
    const float q_ = hi4 ? y : p;
    const float mu  = s_ * (1.0f / 256.0f);
    const float var = q_ * (1.0f / 256.0f) - mu * mu;
    const float r_  = rsqrtf(var + EPS);
    const float msh = -mu * r_;

    // Chunk's total shift (sum over its 4 words).
    float mc = msh + __shfl_xor_sync(0xffffffffu, msh, 8);
    mc += __shfl_xor_sync(0xffffffffu, mc, 16);
    mtot += mc;

    // Broadcast rstd for words 0..3 and accumulate packed.
    #pragma unroll
    for (int wi = 0; wi < 4; wi++) {
        const float rw = __shfl_sync(0xffffffffu, r_, wi * 8);
        const u64 rr = pack2(rw, rw);
        acc[0] = fma2(pack2(R[wi].x, R[wi].y), rr, acc[0]);
        acc[1] = fma2(pack2(R[wi].z, R[wi].w), rr, acc[1]);
        acc[2] = fma2(pack2(R[4 + wi].x, R[4 + wi].y), rr, acc[2]);
        acc[3] = fma2(pack2(R[4 + wi].z, R[4 + wi].w), rr, acc[3]);
    }
}

__global__ __launch_bounds__(256, 2)
void emb_ln_sum_kernel(const int* __restrict__ ids,
                       const float* __restrict__ table,
                       const float* __restrict__ gamma,
                       const float* __restrict__ beta,
                       float* __restrict__ out) {
    const int tid  = threadIdx.x;
    const int warp = tid >> 5;
    const int lane = tid & 31;
    const int pos  = blockIdx.x * 8 + warp;   // 0..4095

    // Lane L holds id of word L for this position (one coalesced LDG.32).
    const int id_lane = __ldg(ids + pos * WORDS + lane);

    // gamma/beta for this lane's dims (loaded once, held in regs).
    const float4 g0 = __ldg((const float4*)gamma + lane);
    const float4 g1 = __ldg((const float4*)gamma + 32 + lane);
    const float4 bt0 = __ldg((const float4*)beta + lane);
    const float4 bt1 = __ldg((const float4*)beta + 32 + lane);

    u64 acc[4];
    const u64 z = pack2(0.0f, 0.0f);
    acc[0] = z; acc[1] = z; acc[2] = z; acc[3] = z;
    float mtot = 0.0f;

    float4 A[8];
    load_chunk(table, id_lane, 0, lane, A);

    #pragma unroll
    for (int c = 0; c < 8; c++) {
        float4 B[8];
        if (c < 7) load_chunk(table, id_lane, c + 1, lane, B);
        process_chunk(A, lane, acc, mtot);
        if (c < 7) {
            #pragma unroll
            for (int k = 0; k < 8; k++) A[k] = B[k];
        }
    }

    // out = (acc + mtot) * gamma + 32 * beta, per lane dims.
    float a0, a1, a2, a3, a4, a5, a6, a7;
    unpack2(acc[0], a0, a1); unpack2(acc[1], a2, a3);
    unpack2(acc[2], a4, a5); unpack2(acc[3], a6, a7);

    float4 o0, o1;
    o0.x = fmaf(a0 + mtot, g0.x, 32.0f * bt0.x);
    o0.y = fmaf(a1 + mtot, g0.y, 32.0f * bt0.y);
    o0.z = fmaf(a2 + mtot, g0.z, 32.0f * bt0.z);
    o0.w = fmaf(a3 + mtot, g0.w, 32.0f * bt0.w);
    o1.x = fmaf(a4 + mtot, g1.x, 32.0f * bt1.x);
    o1.y = fmaf(a5 + mtot, g1.y, 32.0f * bt1.y);
    o1.z = fmaf(a6 + mtot, g1.z, 32.0f * bt1.z);
    o1.w = fmaf(a7 + mtot, g1.w, 32.0f * bt1.w);

    float4* op = (float4*)(out + (size_t)pos * DIM);
    op[lane]      = o0;   // dims [4*lane, 4*lane+4)
    op[32 + lane] = o1;   // dims [128+4*lane, ...)
}

extern "C" void kernel_launch(void* const* d_in, const int* in_sizes, int n_in,
                              void* d_out, int out_size) {
    const int*   ids   = (const int*)d_in[0];     // [32,128,32] int32
    const float* table = (const float*)d_in[1];   // [32000,256] f32
    const float* gamma = (const float*)d_in[2];   // [256]
    const float* beta  = (const float*)d_in[3];   // [256]
    float* out = (float*)d_out;                   // [32,128,256] f32

    const int n_pos = in_sizes[0] / WORDS;        // 4096
    emb_ln_sum_kernel<<<n_pos / 8, 256>>>(ids, table, gamma, beta, out);
}